// round 5
// baseline (speedup 1.0000x reference)
#include <cuda_runtime.h>
#include <mma.h>
#include <math.h>
#include <cstdint>

using namespace nvcuda;

#define NN 100000
#define NN_PAD 100032
#define NE 400000
#define NG 4096
#define TILES 1563          // ceil(NN/64); 1563*64 == 100032 exactly

// ---------------- scratch (static __device__ — no allocations) ----------------
__device__ float g_xpad[(size_t)NN_PAD * 40];
__device__ float g_xl[(size_t)NN_PAD * 128];
__device__ float g_xr[(size_t)NN_PAD * 128];
__device__ float g_xres[(size_t)NN_PAD * 128];
__device__ float g_h[(size_t)NN_PAD * 128];
__device__ int   g_deg[NN];
__device__ int   g_cur[NN];
__device__ int   g_offs[NN + 1];
__device__ int2  g_es[NE];       // (edge id, src node), real edges only
__device__ int   g_bsum[128];
__device__ float g_gsum[(size_t)NG * 128];
__device__ int   g_gcnt[NG];

// ---------------- setup: pad x (stride 40, ones col at 38) + zero counters ----------------
__global__ void setup_kernel(const float* __restrict__ x) {
    int i = blockIdx.x * blockDim.x + threadIdx.x;
    if (i < NN_PAD * 40) {
        int r = i / 40, c = i - r * 40;
        float v;
        if (r < NN && c < 38)      v = x[(size_t)r * 38 + c];
        else if (c == 38)          v = 1.0f;
        else                       v = 0.0f;
        g_xpad[i] = v;
    }
    if (i < NN) { g_deg[i] = 0; g_cur[i] = 0; }
    if (i < NG * 128) g_gsum[i] = 0.f;
    if (i < NG) g_gcnt[i] = 0;
}

// ---------------- degree ----------------
__global__ void deg_kernel(const int* __restrict__ dst) {
    int e = blockIdx.x * blockDim.x + threadIdx.x;
    if (e < NE) atomicAdd(&g_deg[dst[e]], 1);
}

// ---------------- tensor-core tf32 GEMM, 64x64 tile per block ----------------
// out[set][64 rows, 64 cols (half ch)] = A[64, AROW] @ W[set][:, ch*64 +: 64]
// bias folded: W row K = bias, A col AROW = 1 (tail cols when KPAD > AROW).
template <int K, int KPAD, int AROW, int ASTRIDE>
__global__ void __launch_bounds__(256)
mm_tc(const float* __restrict__ A,
      const float* __restrict__ Wa, const float* __restrict__ ba, float* __restrict__ oa,
      const float* __restrict__ Wb, const float* __restrict__ bb, float* __restrict__ ob,
      const float* __restrict__ Wc, const float* __restrict__ bc, float* __restrict__ oc) {
    constexpr int WSTRIDE = 68;
    extern __shared__ float sm[];
    float* Wt = sm;                       // KPAD x 68
    float* At = sm + KPAD * WSTRIDE;      // 64 x ASTRIDE

    int set = blockIdx.y >> 1;
    int ch  = blockIdx.y & 1;
    const float* W = (set == 0) ? Wa : (set == 1) ? Wb : Wc;
    const float* b = (set == 0) ? ba : (set == 1) ? bb : bc;
    float* out     = (set == 0) ? oa : (set == 1) ? ob : oc;

    int row0 = blockIdx.x * 64;

    // A tile via cp.async (AROW % 4 == 0, 16B aligned)
    {
        constexpr int SEGS = AROW / 4;
        for (int i = threadIdx.x; i < 64 * SEGS; i += 256) {
            int r = i / SEGS, seg = i - r * SEGS;
            unsigned d = (unsigned)__cvta_generic_to_shared(At + r * ASTRIDE + seg * 4);
            const float* s = A + (size_t)(row0 + r) * AROW + seg * 4;
            asm volatile("cp.async.cg.shared.global [%0], [%1], 16;" :: "r"(d), "l"(s));
        }
        asm volatile("cp.async.commit_group;");
    }
    // W slice (64 cols), bias row at K, zeros above
    for (int i = threadIdx.x; i < KPAD * 64; i += 256) {
        int k = i >> 6, c = i & 63;
        float v = (k < K) ? W[(size_t)k * 128 + ch * 64 + c]
                          : ((k == K) ? b[ch * 64 + c] : 0.f);
        Wt[k * WSTRIDE + c] = wmma::__float_to_tf32(v);
    }
    // A tail cols (ones col at AROW) when bias row beyond AROW
    if (KPAD > AROW) {
        constexpr int TAIL = KPAD - AROW;
        for (int i = threadIdx.x; i < 64 * TAIL; i += 256) {
            int r = i / TAIL, c = AROW + (i - r * TAIL);
            At[r * ASTRIDE + c] = (c == AROW) ? 1.0f : 0.f;
        }
    }
    asm volatile("cp.async.wait_group 0;");
    __syncthreads();

    int warp = threadIdx.x >> 5;
    int wr = warp >> 1;      // 0..3 -> 16 rows
    int wc = warp & 1;       // 0..1 -> 32 cols

    wmma::fragment<wmma::accumulator, 16, 16, 8, float> acc[2];
    wmma::fill_fragment(acc[0], 0.f);
    wmma::fill_fragment(acc[1], 0.f);

#pragma unroll
    for (int kk = 0; kk < KPAD / 8; ++kk) {
        wmma::fragment<wmma::matrix_a, 16, 16, 8, wmma::precision::tf32,
                       wmma::row_major> af;
        wmma::load_matrix_sync(af, At + wr * 16 * ASTRIDE + kk * 8, ASTRIDE);
#pragma unroll
        for (int e = 0; e < af.num_elements; ++e)
            af.x[e] = wmma::__float_to_tf32(af.x[e]);
#pragma unroll
        for (int j = 0; j < 2; ++j) {
            wmma::fragment<wmma::matrix_b, 16, 16, 8, wmma::precision::tf32,
                           wmma::row_major> bf;
            wmma::load_matrix_sync(bf, Wt + kk * 8 * WSTRIDE + wc * 32 + j * 16, WSTRIDE);
            wmma::mma_sync(acc[j], af, bf, acc[j]);
        }
    }
#pragma unroll
    for (int j = 0; j < 2; ++j)
        wmma::store_matrix_sync(
            out + (size_t)(row0 + wr * 16) * 128 + ch * 64 + wc * 32 + j * 16,
            acc[j], 128, wmma::mem_row_major);
}

// ---------------- scan: CSR offsets from degrees ----------------
__global__ void scan1_kernel() {
    __shared__ int s[1024];
    int n = blockIdx.x * 1024 + threadIdx.x;
    int v = (n < NN) ? g_deg[n] : 0;
    s[threadIdx.x] = v;
    __syncthreads();
    for (int off = 1; off < 1024; off <<= 1) {
        int t = (threadIdx.x >= off) ? s[threadIdx.x - off] : 0;
        __syncthreads();
        s[threadIdx.x] += t;
        __syncthreads();
    }
    if (n < NN) g_offs[n] = s[threadIdx.x] - v;   // exclusive within block
    if (threadIdx.x == 1023) g_bsum[blockIdx.x] = s[1023];
}

__global__ void scan23_kernel(int nb) {
    __shared__ int bsm[128];
    if (threadIdx.x < 128) bsm[threadIdx.x] = (threadIdx.x < nb) ? g_bsum[threadIdx.x] : 0;
    __syncthreads();
    for (int o = 1; o < 128; o <<= 1) {
        int v = 0;
        if (threadIdx.x < 128 && threadIdx.x >= o) v = bsm[threadIdx.x - o];
        __syncthreads();
        if (threadIdx.x < 128) bsm[threadIdx.x] += v;
        __syncthreads();
    }
    int b = blockIdx.x;
    int offset = (b == 0) ? 0 : bsm[b - 1];
    int n = b * 1024 + threadIdx.x;
    if (n < NN) g_offs[n] += offset;
    if (b == 0 && threadIdx.x == 0) g_offs[NN] = NE;
}

// ---------------- scatter (edge id, src) into CSR by dst ----------------
__global__ void scatter_kernel(const int* __restrict__ src,
                               const int* __restrict__ dst) {
    int i = blockIdx.x * blockDim.x + threadIdx.x;
    if (i >= NE) return;
    int node = dst[i];
    int pos = g_offs[node] + atomicAdd(&g_cur[node], 1);
    g_es[pos] = make_int2(i, src[i]);
}

// ---------------- fused GATv2 block ----------------
template <bool BLOCK2>
__global__ void __launch_bounds__(256)
gat_kernel(const float* __restrict__ xl, const float* __restrict__ xr,
           const float* __restrict__ resid, float* __restrict__ hout,
           const float* __restrict__ We, const float* __restrict__ att,
           const float* __restrict__ ab, const float* __restrict__ lng,
           const float* __restrict__ lnb,
           const float* __restrict__ edge_attr, const int* __restrict__ batch) {
    int lane = threadIdx.x & 31;
    int warp = threadIdx.x >> 5;
    int wid = blockIdx.x * 8 + warp;
    int nwarps = gridDim.x * 8;

    float4 Wreg[13];
#pragma unroll
    for (int j = 0; j < 13; ++j)
        Wreg[j] = *(const float4*)&We[j * 128 + lane * 4];

    float4 att4 = ((const float4*)att)[lane];
    float4 ab4  = ((const float4*)ab)[lane];
    float4 lg4  = ((const float4*)lng)[lane];
    float4 lb4  = ((const float4*)lnb)[lane];

    for (int n = wid; n < NN; n += nwarps) {
        int off0 = g_offs[n], off1 = g_offs[n + 1];
        float4 xr4 = ((const float4*)xr)[(size_t)n * 32 + lane];
        float invdeg = 1.f / fmaxf((float)(off1 - off0), 1.f);

        float m = -INFINITY, ss = 0.f;
        float a0 = 0.f, a1 = 0.f, a2 = 0.f, a3 = 0.f;
        float vsum = 0.f;

        int2 esA; float4 xlA; float vA = 0.f;
        if (off0 < off1) {
            esA = g_es[off0];
            xlA = ((const float4*)xl)[(size_t)esA.y * 32 + lane];
            vA = (lane < 13) ? edge_attr[(size_t)esA.x * 13 + lane] : 0.f;
        }

        for (int idx = off0; idx < off1; ++idx) {
            int2 esB; float4 xlB; float vB = 0.f;
            if (idx + 1 < off1) {
                esB = g_es[idx + 1];
                xlB = ((const float4*)xl)[(size_t)esB.y * 32 + lane];
                vB = (lane < 13) ? edge_attr[(size_t)esB.x * 13 + lane] : 0.f;
            }

            vsum += vA;
            float e0 = 0.f, e1 = 0.f, e2 = 0.f, e3 = 0.f;
#pragma unroll
            for (int j = 0; j < 13; ++j) {
                float f = __shfl_sync(0xffffffffu, vA, j);
                e0 += f * Wreg[j].x; e1 += f * Wreg[j].y;
                e2 += f * Wreg[j].z; e3 += f * Wreg[j].w;
            }
            float z0 = xlA.x + xr4.x + e0;
            float z1 = xlA.y + xr4.y + e1;
            float z2 = xlA.z + xr4.z + e2;
            float z3 = xlA.w + xr4.w + e3;
            z0 = z0 > 0.f ? z0 : 0.2f * z0;
            z1 = z1 > 0.f ? z1 : 0.2f * z1;
            z2 = z2 > 0.f ? z2 : 0.2f * z2;
            z3 = z3 > 0.f ? z3 : 0.2f * z3;
            float p = z0 * att4.x + z1 * att4.y + z2 * att4.z + z3 * att4.w;
            p += __shfl_xor_sync(0xffffffffu, p, 1);
            p += __shfl_xor_sync(0xffffffffu, p, 2);
            p += __shfl_xor_sync(0xffffffffu, p, 4);
            float mn = fmaxf(m, p);
            float so = __expf(m - mn);
            float ex = __expf(p - mn);
            ss = ss * so + ex;
            a0 = a0 * so + ex * xlA.x;
            a1 = a1 * so + ex * xlA.y;
            a2 = a2 * so + ex * xlA.z;
            a3 = a3 * so + ex * xlA.w;
            m = mn;

            esA = esB; xlA = xlB; vA = vB;
        }

        // ---- self loop: attr = mean of in-edge attrs, src = n ----
        {
            float vL = vsum * invdeg;
            float e0 = 0.f, e1 = 0.f, e2 = 0.f, e3 = 0.f;
#pragma unroll
            for (int j = 0; j < 13; ++j) {
                float f = __shfl_sync(0xffffffffu, vL, j);
                e0 += f * Wreg[j].x; e1 += f * Wreg[j].y;
                e2 += f * Wreg[j].z; e3 += f * Wreg[j].w;
            }
            float4 xls = ((const float4*)xl)[(size_t)n * 32 + lane];
            float z0 = xls.x + xr4.x + e0;
            float z1 = xls.y + xr4.y + e1;
            float z2 = xls.z + xr4.z + e2;
            float z3 = xls.w + xr4.w + e3;
            z0 = z0 > 0.f ? z0 : 0.2f * z0;
            z1 = z1 > 0.f ? z1 : 0.2f * z1;
            z2 = z2 > 0.f ? z2 : 0.2f * z2;
            z3 = z3 > 0.f ? z3 : 0.2f * z3;
            float p = z0 * att4.x + z1 * att4.y + z2 * att4.z + z3 * att4.w;
            p += __shfl_xor_sync(0xffffffffu, p, 1);
            p += __shfl_xor_sync(0xffffffffu, p, 2);
            p += __shfl_xor_sync(0xffffffffu, p, 4);
            float mn = fmaxf(m, p);
            float so = __expf(m - mn);
            float ex = __expf(p - mn);
            ss = ss * so + ex;
            a0 = a0 * so + ex * xls.x;
            a1 = a1 * so + ex * xls.y;
            a2 = a2 * so + ex * xls.z;
            a3 = a3 * so + ex * xls.w;
        }

        float inv = 1.f / ss;
        float t0 = a0 * inv + ab4.x;
        float t1 = a1 * inv + ab4.y;
        float t2 = a2 * inv + ab4.z;
        float t3 = a3 * inv + ab4.w;
        t0 = t0 > 0.f ? t0 : expm1f(t0);
        t1 = t1 > 0.f ? t1 : expm1f(t1);
        t2 = t2 > 0.f ? t2 : expm1f(t2);
        t3 = t3 > 0.f ? t3 : expm1f(t3);
        float4 r4 = ((const float4*)resid)[(size_t)n * 32 + lane];
        t0 += r4.x; t1 += r4.y; t2 += r4.z; t3 += r4.w;
        float s1 = t0 + t1 + t2 + t3;
#pragma unroll
        for (int o = 1; o < 32; o <<= 1) s1 += __shfl_xor_sync(0xffffffffu, s1, o);
        float mu = s1 * (1.f / 128.f);
        float d0 = t0 - mu, d1 = t1 - mu, d2 = t2 - mu, d3 = t3 - mu;
        float s2 = d0 * d0 + d1 * d1 + d2 * d2 + d3 * d3;
#pragma unroll
        for (int o = 1; o < 32; o <<= 1) s2 += __shfl_xor_sync(0xffffffffu, s2, o);
        float rstd = rsqrtf(s2 * (1.f / 128.f) + 1e-5f);
        float o0 = d0 * rstd * lg4.x + lb4.x;
        float o1 = d1 * rstd * lg4.y + lb4.y;
        float o2 = d2 * rstd * lg4.z + lb4.z;
        float o3 = d3 * rstd * lg4.w + lb4.w;

        if (!BLOCK2) {
            ((float4*)hout)[(size_t)n * 32 + lane] = make_float4(o0, o1, o2, o3);
        } else {
            int g = batch[n];
            float* gs = g_gsum + (size_t)g * 128 + lane * 4;
            atomicAdd(gs + 0, o0);
            atomicAdd(gs + 1, o1);
            atomicAdd(gs + 2, o2);
            atomicAdd(gs + 3, o3);
            if (lane == 0) atomicAdd(&g_gcnt[g], 1);
        }
    }
}

// ---------------- readout: warp per graph ----------------
__global__ void __launch_bounds__(256)
readout_kernel(const float* __restrict__ Wd1, const float* __restrict__ bd1,
               const float* __restrict__ Wd2, const float* __restrict__ bd2,
               float* __restrict__ out) {
    __shared__ float sm[8][128];
    int lane = threadIdx.x & 31;
    int warp = threadIdx.x >> 5;
    int g = blockIdx.x * 8 + warp;
    if (g >= NG) return;

    int cnt = g_gcnt[g];
    float inv = 1.f / fmaxf((float)cnt, 1.f);
    float4 m4 = ((const float4*)g_gsum)[(size_t)g * 32 + lane];
    sm[warp][lane * 4 + 0] = m4.x * inv;
    sm[warp][lane * 4 + 1] = m4.y * inv;
    sm[warp][lane * 4 + 2] = m4.z * inv;
    sm[warp][lane * 4 + 3] = m4.w * inv;
    __syncwarp();

    float h0 = bd1[lane], h1 = bd1[lane + 32];
#pragma unroll 4
    for (int d = 0; d < 128; ++d) {
        float md = sm[warp][d];
        h0 += md * Wd1[d * 64 + lane];
        h1 += md * Wd1[d * 64 + lane + 32];
    }
    h0 = fmaxf(h0, 0.f);
    h1 = fmaxf(h1, 0.f);
    float p = h0 * Wd2[lane] + h1 * Wd2[lane + 32];
#pragma unroll
    for (int o = 1; o < 32; o <<= 1) p += __shfl_xor_sync(0xffffffffu, p, o);
    if (lane == 0) out[g] = p + bd2[0];
}

// ---------------- launch ----------------
extern "C" void kernel_launch(void* const* d_in, const int* in_sizes, int n_in,
                              void* d_out, int out_size) {
    const float* x         = (const float*)d_in[0];
    const int*   edge_idx  = (const int*)d_in[1];
    const float* edge_attr = (const float*)d_in[2];
    const int*   batch     = (const int*)d_in[3];
    const float* Wl1 = (const float*)d_in[4];
    const float* bl1 = (const float*)d_in[5];
    const float* Wr1 = (const float*)d_in[6];
    const float* br1 = (const float*)d_in[7];
    const float* We1 = (const float*)d_in[8];
    const float* att1 = (const float*)d_in[9];
    const float* ab1 = (const float*)d_in[10];
    const float* lng1 = (const float*)d_in[11];
    const float* lnb1 = (const float*)d_in[12];
    const float* Wres = (const float*)d_in[13];
    const float* bres = (const float*)d_in[14];
    const float* Wl2 = (const float*)d_in[15];
    const float* bl2 = (const float*)d_in[16];
    const float* Wr2 = (const float*)d_in[17];
    const float* br2 = (const float*)d_in[18];
    const float* We2 = (const float*)d_in[19];
    const float* att2 = (const float*)d_in[20];
    const float* ab2 = (const float*)d_in[21];
    const float* lng2 = (const float*)d_in[22];
    const float* lnb2 = (const float*)d_in[23];
    const float* Wd1 = (const float*)d_in[24];
    const float* bd1 = (const float*)d_in[25];
    const float* Wd2 = (const float*)d_in[26];
    const float* bd2 = (const float*)d_in[27];
    float* out = (float*)d_out;

    const int* src = edge_idx;
    const int* dst = edge_idx + NE;

    float *p_xpad, *p_xl, *p_xr, *p_xres, *p_h;
    cudaGetSymbolAddress((void**)&p_xpad, g_xpad);
    cudaGetSymbolAddress((void**)&p_xl, g_xl);
    cudaGetSymbolAddress((void**)&p_xr, g_xr);
    cudaGetSymbolAddress((void**)&p_xres, g_xres);
    cudaGetSymbolAddress((void**)&p_h, g_h);

    int smem1 = (40 * 68 + 64 * 48) * 4;     // 23168 B
    int smem2 = (136 * 68 + 64 * 144) * 4;   // 73856 B
    cudaFuncSetAttribute((const void*)mm_tc<38, 40, 40, 48>,
                         cudaFuncAttributeMaxDynamicSharedMemorySize, smem1);
    cudaFuncSetAttribute((const void*)mm_tc<128, 136, 128, 144>,
                         cudaFuncAttributeMaxDynamicSharedMemorySize, smem2);

    int nb = (NN + 1023) / 1024;
    // launch order: slot 4 (ncu-sampled) = block-1 GEMM
    setup_kernel<<<(NN_PAD * 40 + 255) / 256, 256>>>(x);
    deg_kernel<<<(NE + 255) / 256, 256>>>(dst);
    scan1_kernel<<<nb, 1024>>>();
    mm_tc<38, 40, 40, 48><<<dim3(TILES, 6), 256, smem1>>>(
        p_xpad, Wl1, bl1, p_xl, Wr1, br1, p_xr, Wres, bres, p_xres);
    scan23_kernel<<<nb, 1024>>>(nb);
    scatter_kernel<<<(NE + 255) / 256, 256>>>(src, dst);
    gat_kernel<false><<<2048, 256>>>(p_xl, p_xr, p_xres, p_h,
                                     We1, att1, ab1, lng1, lnb1,
                                     edge_attr, nullptr);
    mm_tc<128, 136, 128, 144><<<dim3(TILES, 4), 256, smem2>>>(
        p_h, Wl2, bl2, p_xl, Wr2, br2, p_xr, Wr2, br2, p_xr);
    gat_kernel<true><<<2048, 256>>>(p_xl, p_xr, p_h, nullptr,
                                    We2, att2, ab2, lng2, lnb2,
                                    edge_attr, batch);
    readout_kernel<<<(NG + 7) / 8, 256>>>(Wd1, bd1, Wd2, bd2, out);
}

// round 6
// speedup vs baseline: 1.0689x; 1.0689x over previous
#include <cuda_runtime.h>
#include <mma.h>
#include <math.h>
#include <cstdint>

using namespace nvcuda;

#define NN 100000
#define NN_PAD 100096
#define NE 400000
#define NG 4096
#define RT128 782           // ceil(NN/128); 782*128 == 100096

typedef unsigned long long u64;

__device__ __forceinline__ u64 pack2(float x, float y) {
    u64 r; asm("mov.b64 %0,{%1,%2};" : "=l"(r) : "f"(x), "f"(y)); return r;
}
__device__ __forceinline__ void unpack2(u64 v, float& x, float& y) {
    asm("mov.b64 {%0,%1},%2;" : "=f"(x), "=f"(y) : "l"(v));
}
__device__ __forceinline__ u64 ffma2(u64 a, u64 b, u64 c) {
    u64 d; asm("fma.rn.f32x2 %0,%1,%2,%3;" : "=l"(d) : "l"(a), "l"(b), "l"(c)); return d;
}
__device__ __forceinline__ u64 fadd2(u64 a, u64 b) {
    u64 d; asm("add.rn.f32x2 %0,%1,%2;" : "=l"(d) : "l"(a), "l"(b)); return d;
}
__device__ __forceinline__ u64 fmul2(u64 a, u64 b) {
    u64 d; asm("mul.rn.f32x2 %0,%1,%2;" : "=l"(d) : "l"(a), "l"(b)); return d;
}

// ---------------- scratch (static __device__ — no allocations) ----------------
__device__ float g_xpad[(size_t)NN_PAD * 40];
__device__ float g_xl[(size_t)NN_PAD * 128];
__device__ float g_xr[(size_t)NN_PAD * 128];
__device__ float g_xres[(size_t)NN_PAD * 128];
__device__ float g_h[(size_t)NN_PAD * 128];
__device__ int   g_deg[NN];
__device__ int   g_cur[NN];
__device__ int   g_offs[NN + 1];
__device__ int2  g_es[NE];       // (edge id, src node)
__device__ int   g_bsum[128];
__device__ float g_gsum[(size_t)NG * 128];
__device__ int   g_gcnt[NG];

// ---------------- setup: pad x (stride 40, ones col at 38) + zero counters ----------------
__global__ void setup_kernel(const float* __restrict__ x) {
    int i = blockIdx.x * blockDim.x + threadIdx.x;
    if (i < NN_PAD * 40) {
        int r = i / 40, c = i - r * 40;
        float v;
        if (r < NN && c < 38)      v = x[(size_t)r * 38 + c];
        else if (c == 38)          v = 1.0f;
        else                       v = 0.0f;
        g_xpad[i] = v;
    }
    if (i < NN) { g_deg[i] = 0; g_cur[i] = 0; }
    if (i < NG * 128) g_gsum[i] = 0.f;
    if (i < NG) g_gcnt[i] = 0;
}

// ---------------- degree ----------------
__global__ void deg_kernel(const int* __restrict__ dst) {
    int e = blockIdx.x * blockDim.x + threadIdx.x;
    if (e < NE) atomicAdd(&g_deg[dst[e]], 1);
}

// ---------------- tensor-core tf32 GEMM, 128x64 block tile, 32x32 warp tile ----------------
// out[set][128 rows, 64 cols (half ch)] = A[128, AROW] @ W[set][:, ch*64 +: 64]
// bias folded: W row K = bias, A col with ones aligns (xpad col 38 / tail col 128).
template <int K, int KPAD, int AROW, int ASTRIDE>
__global__ void __launch_bounds__(256)
mm_tc(const float* __restrict__ A,
      const float* __restrict__ Wa, const float* __restrict__ ba, float* __restrict__ oa,
      const float* __restrict__ Wb, const float* __restrict__ bb, float* __restrict__ ob,
      const float* __restrict__ Wc, const float* __restrict__ bc, float* __restrict__ oc) {
    constexpr int WSTRIDE = 68;
    extern __shared__ float sm[];
    float* Wt = sm;                       // KPAD x 68
    float* At = sm + KPAD * WSTRIDE;      // 128 x ASTRIDE

    int set = blockIdx.y >> 1;
    int ch  = blockIdx.y & 1;
    const float* W = (set == 0) ? Wa : (set == 1) ? Wb : Wc;
    const float* b = (set == 0) ? ba : (set == 1) ? bb : bc;
    float* out     = (set == 0) ? oa : (set == 1) ? ob : oc;

    int row0 = blockIdx.x * 128;

    // A tile via cp.async
    {
        constexpr int SEGS = AROW / 4;
        for (int i = threadIdx.x; i < 128 * SEGS; i += 256) {
            int r = i / SEGS, seg = i - r * SEGS;
            unsigned d = (unsigned)__cvta_generic_to_shared(At + r * ASTRIDE + seg * 4);
            const float* s = A + (size_t)(row0 + r) * AROW + seg * 4;
            asm volatile("cp.async.cg.shared.global [%0], [%1], 16;" :: "r"(d), "l"(s));
        }
        asm volatile("cp.async.commit_group;");
    }
    // W slice (64 cols), bias row at K, zeros above
    for (int i = threadIdx.x; i < KPAD * 64; i += 256) {
        int k = i >> 6, c = i & 63;
        float v = (k < K) ? W[(size_t)k * 128 + ch * 64 + c]
                          : ((k == K) ? b[ch * 64 + c] : 0.f);
        Wt[k * WSTRIDE + c] = wmma::__float_to_tf32(v);
    }
    // A tail cols (ones col at AROW) when bias row beyond AROW
    if (KPAD > AROW) {
        constexpr int TAIL = KPAD - AROW;
        for (int i = threadIdx.x; i < 128 * TAIL; i += 256) {
            int r = i / TAIL, c = AROW + (i - r * TAIL);
            At[r * ASTRIDE + c] = (c == AROW) ? 1.0f : 0.f;
        }
    }
    asm volatile("cp.async.wait_group 0;");
    __syncthreads();

    int warp = threadIdx.x >> 5;
    int wr = warp >> 1;      // 0..3 -> 32 rows each
    int wc = warp & 1;       // 0..1 -> 32 cols each

    wmma::fragment<wmma::accumulator, 16, 16, 8, float> acc[2][2];
#pragma unroll
    for (int i = 0; i < 2; ++i)
#pragma unroll
        for (int j = 0; j < 2; ++j) wmma::fill_fragment(acc[i][j], 0.f);

#pragma unroll
    for (int kk = 0; kk < KPAD / 8; ++kk) {
        wmma::fragment<wmma::matrix_a, 16, 16, 8, wmma::precision::tf32,
                       wmma::row_major> af[2];
#pragma unroll
        for (int i = 0; i < 2; ++i) {
            wmma::load_matrix_sync(af[i],
                At + (wr * 32 + i * 16) * ASTRIDE + kk * 8, ASTRIDE);
#pragma unroll
            for (int e = 0; e < af[i].num_elements; ++e)
                af[i].x[e] = wmma::__float_to_tf32(af[i].x[e]);
        }
        wmma::fragment<wmma::matrix_b, 16, 16, 8, wmma::precision::tf32,
                       wmma::row_major> bf[2];
#pragma unroll
        for (int j = 0; j < 2; ++j)
            wmma::load_matrix_sync(bf[j],
                Wt + kk * 8 * WSTRIDE + wc * 32 + j * 16, WSTRIDE);
#pragma unroll
        for (int i = 0; i < 2; ++i)
#pragma unroll
            for (int j = 0; j < 2; ++j)
                wmma::mma_sync(acc[i][j], af[i], bf[j], acc[i][j]);
    }
#pragma unroll
    for (int i = 0; i < 2; ++i)
#pragma unroll
        for (int j = 0; j < 2; ++j)
            wmma::store_matrix_sync(
                out + (size_t)(row0 + wr * 32 + i * 16) * 128 + ch * 64 + wc * 32 + j * 16,
                acc[i][j], 128, wmma::mem_row_major);
}

// ---------------- scan: CSR offsets from degrees ----------------
__global__ void scan1_kernel() {
    __shared__ int s[1024];
    int n = blockIdx.x * 1024 + threadIdx.x;
    int v = (n < NN) ? g_deg[n] : 0;
    s[threadIdx.x] = v;
    __syncthreads();
    for (int off = 1; off < 1024; off <<= 1) {
        int t = (threadIdx.x >= off) ? s[threadIdx.x - off] : 0;
        __syncthreads();
        s[threadIdx.x] += t;
        __syncthreads();
    }
    if (n < NN) g_offs[n] = s[threadIdx.x] - v;
    if (threadIdx.x == 1023) g_bsum[blockIdx.x] = s[1023];
}

__global__ void scan23_kernel(int nb) {
    __shared__ int bsm[128];
    if (threadIdx.x < 128) bsm[threadIdx.x] = (threadIdx.x < nb) ? g_bsum[threadIdx.x] : 0;
    __syncthreads();
    for (int o = 1; o < 128; o <<= 1) {
        int v = 0;
        if (threadIdx.x < 128 && threadIdx.x >= o) v = bsm[threadIdx.x - o];
        __syncthreads();
        if (threadIdx.x < 128) bsm[threadIdx.x] += v;
        __syncthreads();
    }
    int b = blockIdx.x;
    int offset = (b == 0) ? 0 : bsm[b - 1];
    int n = b * 1024 + threadIdx.x;
    if (n < NN) g_offs[n] += offset;
    if (b == 0 && threadIdx.x == 0) g_offs[NN] = NE;
}

// ---------------- scatter (edge id, src) into CSR by dst ----------------
__global__ void scatter_kernel(const int* __restrict__ src,
                               const int* __restrict__ dst) {
    int i = blockIdx.x * blockDim.x + threadIdx.x;
    if (i >= NE) return;
    int node = dst[i];
    int pos = g_offs[node] + atomicAdd(&g_cur[node], 1);
    g_es[pos] = make_int2(i, src[i]);
}

// ---------------- fused GATv2 block (f32x2-packed inner loop) ----------------
template <bool BLOCK2>
__global__ void __launch_bounds__(256)
gat_kernel(const float* __restrict__ xl, const float* __restrict__ xr,
           const float* __restrict__ resid, float* __restrict__ hout,
           const float* __restrict__ We, const float* __restrict__ att,
           const float* __restrict__ ab, const float* __restrict__ lng,
           const float* __restrict__ lnb,
           const float* __restrict__ edge_attr, const int* __restrict__ batch) {
    int lane = threadIdx.x & 31;
    int warp = threadIdx.x >> 5;
    int wid = blockIdx.x * 8 + warp;
    int nwarps = gridDim.x * 8;

    u64 Wp[13][2];
#pragma unroll
    for (int j = 0; j < 13; ++j) {
        float4 w = *(const float4*)&We[j * 128 + lane * 4];
        Wp[j][0] = pack2(w.x, w.y);
        Wp[j][1] = pack2(w.z, w.w);
    }

    float4 att4 = ((const float4*)att)[lane];
    float4 ab4  = ((const float4*)ab)[lane];
    float4 lg4  = ((const float4*)lng)[lane];
    float4 lb4  = ((const float4*)lnb)[lane];

    for (int n = wid; n < NN; n += nwarps) {
        int off0 = g_offs[n], off1 = g_offs[n + 1];
        float4 xr4 = ((const float4*)xr)[(size_t)n * 32 + lane];
        u64 xr01 = pack2(xr4.x, xr4.y), xr23 = pack2(xr4.z, xr4.w);
        float invdeg = 1.f / fmaxf((float)(off1 - off0), 1.f);

        float m = -INFINITY, ss = 0.f;
        u64 a01 = 0ull, a23 = 0ull;
        float vsum = 0.f;

        int2 esA; float4 xlA; float vA = 0.f;
        if (off0 < off1) {
            esA = g_es[off0];
            xlA = ((const float4*)xl)[(size_t)esA.y * 32 + lane];
            vA = (lane < 13) ? edge_attr[(size_t)esA.x * 13 + lane] : 0.f;
        }

        for (int idx = off0; idx < off1; ++idx) {
            int2 esB; float4 xlB; float vB = 0.f;
            if (idx + 1 < off1) {
                esB = g_es[idx + 1];
                xlB = ((const float4*)xl)[(size_t)esB.y * 32 + lane];
                vB = (lane < 13) ? edge_attr[(size_t)esB.x * 13 + lane] : 0.f;
            }

            vsum += vA;
            u64 e01 = 0ull, e23 = 0ull;
#pragma unroll
            for (int j = 0; j < 13; ++j) {
                float f = __shfl_sync(0xffffffffu, vA, j);
                u64 ff = pack2(f, f);
                e01 = ffma2(ff, Wp[j][0], e01);
                e23 = ffma2(ff, Wp[j][1], e23);
            }
            u64 xl01 = pack2(xlA.x, xlA.y), xl23 = pack2(xlA.z, xlA.w);
            u64 z01 = fadd2(fadd2(xl01, xr01), e01);
            u64 z23 = fadd2(fadd2(xl23, xr23), e23);
            float z0, z1, z2, z3;
            unpack2(z01, z0, z1);
            unpack2(z23, z2, z3);
            z0 = fmaxf(z0, 0.2f * z0);
            z1 = fmaxf(z1, 0.2f * z1);
            z2 = fmaxf(z2, 0.2f * z2);
            z3 = fmaxf(z3, 0.2f * z3);
            float p = z0 * att4.x + z1 * att4.y + z2 * att4.z + z3 * att4.w;
            p += __shfl_xor_sync(0xffffffffu, p, 1);
            p += __shfl_xor_sync(0xffffffffu, p, 2);
            p += __shfl_xor_sync(0xffffffffu, p, 4);
            float mn = fmaxf(m, p);
            float so = __expf(m - mn);
            float ex = __expf(p - mn);
            ss = ss * so + ex;
            u64 so2 = pack2(so, so), ex2 = pack2(ex, ex);
            a01 = ffma2(ex2, xl01, fmul2(a01, so2));
            a23 = ffma2(ex2, xl23, fmul2(a23, so2));
            m = mn;

            esA = esB; xlA = xlB; vA = vB;
        }

        // ---- self loop: attr = mean of in-edge attrs, src = n ----
        {
            float vL = vsum * invdeg;
            u64 e01 = 0ull, e23 = 0ull;
#pragma unroll
            for (int j = 0; j < 13; ++j) {
                float f = __shfl_sync(0xffffffffu, vL, j);
                u64 ff = pack2(f, f);
                e01 = ffma2(ff, Wp[j][0], e01);
                e23 = ffma2(ff, Wp[j][1], e23);
            }
            float4 xls = ((const float4*)xl)[(size_t)n * 32 + lane];
            u64 xl01 = pack2(xls.x, xls.y), xl23 = pack2(xls.z, xls.w);
            u64 z01 = fadd2(fadd2(xl01, xr01), e01);
            u64 z23 = fadd2(fadd2(xl23, xr23), e23);
            float z0, z1, z2, z3;
            unpack2(z01, z0, z1);
            unpack2(z23, z2, z3);
            z0 = fmaxf(z0, 0.2f * z0);
            z1 = fmaxf(z1, 0.2f * z1);
            z2 = fmaxf(z2, 0.2f * z2);
            z3 = fmaxf(z3, 0.2f * z3);
            float p = z0 * att4.x + z1 * att4.y + z2 * att4.z + z3 * att4.w;
            p += __shfl_xor_sync(0xffffffffu, p, 1);
            p += __shfl_xor_sync(0xffffffffu, p, 2);
            p += __shfl_xor_sync(0xffffffffu, p, 4);
            float mn = fmaxf(m, p);
            float so = __expf(m - mn);
            float ex = __expf(p - mn);
            ss = ss * so + ex;
            u64 so2 = pack2(so, so), ex2 = pack2(ex, ex);
            a01 = ffma2(ex2, xl01, fmul2(a01, so2));
            a23 = ffma2(ex2, xl23, fmul2(a23, so2));
        }

        float a0, a1, a2, a3;
        unpack2(a01, a0, a1);
        unpack2(a23, a2, a3);
        float inv = 1.f / ss;
        float t0 = a0 * inv + ab4.x;
        float t1 = a1 * inv + ab4.y;
        float t2 = a2 * inv + ab4.z;
        float t3 = a3 * inv + ab4.w;
        t0 = t0 > 0.f ? t0 : expm1f(t0);
        t1 = t1 > 0.f ? t1 : expm1f(t1);
        t2 = t2 > 0.f ? t2 : expm1f(t2);
        t3 = t3 > 0.f ? t3 : expm1f(t3);
        float4 r4 = ((const float4*)resid)[(size_t)n * 32 + lane];
        t0 += r4.x; t1 += r4.y; t2 += r4.z; t3 += r4.w;
        float s1 = t0 + t1 + t2 + t3;
#pragma unroll
        for (int o = 1; o < 32; o <<= 1) s1 += __shfl_xor_sync(0xffffffffu, s1, o);
        float mu = s1 * (1.f / 128.f);
        float d0 = t0 - mu, d1 = t1 - mu, d2 = t2 - mu, d3 = t3 - mu;
        float s2 = d0 * d0 + d1 * d1 + d2 * d2 + d3 * d3;
#pragma unroll
        for (int o = 1; o < 32; o <<= 1) s2 += __shfl_xor_sync(0xffffffffu, s2, o);
        float rstd = rsqrtf(s2 * (1.f / 128.f) + 1e-5f);
        float o0 = d0 * rstd * lg4.x + lb4.x;
        float o1 = d1 * rstd * lg4.y + lb4.y;
        float o2 = d2 * rstd * lg4.z + lb4.z;
        float o3 = d3 * rstd * lg4.w + lb4.w;

        if (!BLOCK2) {
            ((float4*)hout)[(size_t)n * 32 + lane] = make_float4(o0, o1, o2, o3);
        } else {
            int g = batch[n];
            float* gs = g_gsum + (size_t)g * 128 + lane * 4;
            atomicAdd(gs + 0, o0);
            atomicAdd(gs + 1, o1);
            atomicAdd(gs + 2, o2);
            atomicAdd(gs + 3, o3);
            if (lane == 0) atomicAdd(&g_gcnt[g], 1);
        }
    }
}

// ---------------- readout: warp per graph ----------------
__global__ void __launch_bounds__(256)
readout_kernel(const float* __restrict__ Wd1, const float* __restrict__ bd1,
               const float* __restrict__ Wd2, const float* __restrict__ bd2,
               float* __restrict__ out) {
    __shared__ float sm[8][128];
    int lane = threadIdx.x & 31;
    int warp = threadIdx.x >> 5;
    int g = blockIdx.x * 8 + warp;
    if (g >= NG) return;

    int cnt = g_gcnt[g];
    float inv = 1.f / fmaxf((float)cnt, 1.f);
    float4 m4 = ((const float4*)g_gsum)[(size_t)g * 32 + lane];
    sm[warp][lane * 4 + 0] = m4.x * inv;
    sm[warp][lane * 4 + 1] = m4.y * inv;
    sm[warp][lane * 4 + 2] = m4.z * inv;
    sm[warp][lane * 4 + 3] = m4.w * inv;
    __syncwarp();

    float h0 = bd1[lane], h1 = bd1[lane + 32];
#pragma unroll 4
    for (int d = 0; d < 128; ++d) {
        float md = sm[warp][d];
        h0 += md * Wd1[d * 64 + lane];
        h1 += md * Wd1[d * 64 + lane + 32];
    }
    h0 = fmaxf(h0, 0.f);
    h1 = fmaxf(h1, 0.f);
    float p = h0 * Wd2[lane] + h1 * Wd2[lane + 32];
#pragma unroll
    for (int o = 1; o < 32; o <<= 1) p += __shfl_xor_sync(0xffffffffu, p, o);
    if (lane == 0) out[g] = p + bd2[0];
}

// ---------------- launch ----------------
extern "C" void kernel_launch(void* const* d_in, const int* in_sizes, int n_in,
                              void* d_out, int out_size) {
    const float* x         = (const float*)d_in[0];
    const int*   edge_idx  = (const int*)d_in[1];
    const float* edge_attr = (const float*)d_in[2];
    const int*   batch     = (const int*)d_in[3];
    const float* Wl1 = (const float*)d_in[4];
    const float* bl1 = (const float*)d_in[5];
    const float* Wr1 = (const float*)d_in[6];
    const float* br1 = (const float*)d_in[7];
    const float* We1 = (const float*)d_in[8];
    const float* att1 = (const float*)d_in[9];
    const float* ab1 = (const float*)d_in[10];
    const float* lng1 = (const float*)d_in[11];
    const float* lnb1 = (const float*)d_in[12];
    const float* Wres = (const float*)d_in[13];
    const float* bres = (const float*)d_in[14];
    const float* Wl2 = (const float*)d_in[15];
    const float* bl2 = (const float*)d_in[16];
    const float* Wr2 = (const float*)d_in[17];
    const float* br2 = (const float*)d_in[18];
    const float* We2 = (const float*)d_in[19];
    const float* att2 = (const float*)d_in[20];
    const float* ab2 = (const float*)d_in[21];
    const float* lng2 = (const float*)d_in[22];
    const float* lnb2 = (const float*)d_in[23];
    const float* Wd1 = (const float*)d_in[24];
    const float* bd1 = (const float*)d_in[25];
    const float* Wd2 = (const float*)d_in[26];
    const float* bd2 = (const float*)d_in[27];
    float* out = (float*)d_out;

    const int* src = edge_idx;
    const int* dst = edge_idx + NE;

    float *p_xpad, *p_xl, *p_xr, *p_xres, *p_h;
    cudaGetSymbolAddress((void**)&p_xpad, g_xpad);
    cudaGetSymbolAddress((void**)&p_xl, g_xl);
    cudaGetSymbolAddress((void**)&p_xr, g_xr);
    cudaGetSymbolAddress((void**)&p_xres, g_xres);
    cudaGetSymbolAddress((void**)&p_h, g_h);

    int smem1 = (40 * 68 + 128 * 48) * 4;     // 35456 B
    int smem2 = (136 * 68 + 128 * 144) * 4;   // 110720 B
    cudaFuncSetAttribute((const void*)mm_tc<38, 40, 40, 48>,
                         cudaFuncAttributeMaxDynamicSharedMemorySize, smem1);
    cudaFuncSetAttribute((const void*)mm_tc<128, 136, 128, 144>,
                         cudaFuncAttributeMaxDynamicSharedMemorySize, smem2);

    int nb = (NN + 1023) / 1024;
    // launch order: slot 4 (ncu-sampled) = block-1 GEMM
    setup_kernel<<<(NN_PAD * 40 + 255) / 256, 256>>>(x);
    deg_kernel<<<(NE + 255) / 256, 256>>>(dst);
    scan1_kernel<<<nb, 1024>>>();
    mm_tc<38, 40, 40, 48><<<dim3(RT128, 6), 256, smem1>>>(
        p_xpad, Wl1, bl1, p_xl, Wr1, br1, p_xr, Wres, bres, p_xres);
    scan23_kernel<<<nb, 1024>>>(nb);
    scatter_kernel<<<(NE + 255) / 256, 256>>>(src, dst);
    gat_kernel<false><<<2048, 256>>>(p_xl, p_xr, p_xres, p_h,
                                     We1, att1, ab1, lng1, lnb1,
                                     edge_attr, nullptr);
    mm_tc<128, 136, 128, 144><<<dim3(RT128, 4), 256, smem2>>>(
        p_h, Wl2, bl2, p_xl, Wr2, br2, p_xr, Wr2, br2, p_xr);
    gat_kernel<true><<<2048, 256>>>(p_xl, p_xr, p_h, nullptr,
                                    We2, att2, ab2, lng2, lnb2,
                                    edge_attr, batch);
    readout_kernel<<<(NG + 7) / 8, 256>>>(Wd1, bd1, Wd2, bd2, out);
}

// round 7
// speedup vs baseline: 1.0997x; 1.0288x over previous
#include <cuda_runtime.h>
#include <mma.h>
#include <math.h>
#include <cstdint>

using namespace nvcuda;

#define NN 100000
#define NN_PAD 100096
#define NE 400000
#define NG 4096
#define RT128 782           // ceil(NN/128); 782*128 == 100096

typedef unsigned long long u64;

__device__ __forceinline__ u64 pack2(float x, float y) {
    u64 r; asm("mov.b64 %0,{%1,%2};" : "=l"(r) : "f"(x), "f"(y)); return r;
}
__device__ __forceinline__ void unpack2(u64 v, float& x, float& y) {
    asm("mov.b64 {%0,%1},%2;" : "=f"(x), "=f"(y) : "l"(v));
}
__device__ __forceinline__ u64 ffma2(u64 a, u64 b, u64 c) {
    u64 d; asm("fma.rn.f32x2 %0,%1,%2,%3;" : "=l"(d) : "l"(a), "l"(b), "l"(c)); return d;
}
__device__ __forceinline__ u64 fadd2(u64 a, u64 b) {
    u64 d; asm("add.rn.f32x2 %0,%1,%2;" : "=l"(d) : "l"(a), "l"(b)); return d;
}
__device__ __forceinline__ u64 fmul2(u64 a, u64 b) {
    u64 d; asm("mul.rn.f32x2 %0,%1,%2;" : "=l"(d) : "l"(a), "l"(b)); return d;
}

// ---------------- scratch (static __device__ — no allocations) ----------------
__device__ float g_xpad[(size_t)NN_PAD * 40];
__device__ float g_xl[(size_t)NN_PAD * 128];
__device__ float g_xr[(size_t)NN_PAD * 128];
__device__ float g_xres[(size_t)NN_PAD * 128];
__device__ float g_h[(size_t)NN_PAD * 128];
__device__ int   g_deg[NN];
__device__ int   g_cur[NN];
__device__ int   g_offs[NN + 1];
__device__ int2  g_es[NE];       // (edge id, src node)
__device__ int   g_bsum[128];
__device__ float g_gsum[(size_t)NG * 128];
__device__ int   g_gcnt[NG];

// ---------------- setup: pad x (stride 40, ones col at 38) + zero counters ----------------
__global__ void setup_kernel(const float* __restrict__ x) {
    int i = blockIdx.x * blockDim.x + threadIdx.x;
    if (i < NN_PAD * 40) {
        int r = i / 40, c = i - r * 40;
        float v;
        if (r < NN && c < 38)      v = x[(size_t)r * 38 + c];
        else if (c == 38)          v = 1.0f;
        else                       v = 0.0f;
        g_xpad[i] = v;
    }
    if (i < NN) { g_deg[i] = 0; g_cur[i] = 0; }
    if (i < NG * 128) g_gsum[i] = 0.f;
    if (i < NG) g_gcnt[i] = 0;
}

// ---------------- degree ----------------
__global__ void deg_kernel(const int* __restrict__ dst) {
    int e = blockIdx.x * blockDim.x + threadIdx.x;
    if (e < NE) atomicAdd(&g_deg[dst[e]], 1);
}

// ---------------- tensor-core tf32 GEMM, 128x64 block tile, 32x32 warp tile ----------------
// A converted to tf32 (RN) during the smem fill — no per-fragment cvt in the kk loop.
template <int K, int KPAD, int AROW, int ASTRIDE>
__global__ void __launch_bounds__(256)
mm_tc(const float* __restrict__ A,
      const float* __restrict__ Wa, const float* __restrict__ ba, float* __restrict__ oa,
      const float* __restrict__ Wb, const float* __restrict__ bb, float* __restrict__ ob,
      const float* __restrict__ Wc, const float* __restrict__ bc, float* __restrict__ oc) {
    constexpr int WSTRIDE = 68;
    extern __shared__ float sm[];
    float* Wt = sm;                       // KPAD x 68
    float* At = sm + KPAD * WSTRIDE;      // 128 x ASTRIDE

    int set = blockIdx.y >> 1;
    int ch  = blockIdx.y & 1;
    const float* W = (set == 0) ? Wa : (set == 1) ? Wb : Wc;
    const float* b = (set == 0) ? ba : (set == 1) ? bb : bc;
    float* out     = (set == 0) ? oa : (set == 1) ? ob : oc;

    int row0 = blockIdx.x * 128;

    // A tile: LDG.128 + cvt(RN) + STS.128
    {
        constexpr int SEGS = AROW / 4;
#pragma unroll
        for (int i = threadIdx.x; i < 128 * SEGS; i += 256) {
            int r = i / SEGS, seg = i - r * SEGS;
            float4 v = *(const float4*)(A + (size_t)(row0 + r) * AROW + seg * 4);
            v.x = wmma::__float_to_tf32(v.x);
            v.y = wmma::__float_to_tf32(v.y);
            v.z = wmma::__float_to_tf32(v.z);
            v.w = wmma::__float_to_tf32(v.w);
            *(float4*)(At + r * ASTRIDE + seg * 4) = v;
        }
    }
    // W slice (64 cols), bias row at K, zeros above
    for (int i = threadIdx.x; i < KPAD * 64; i += 256) {
        int k = i >> 6, c = i & 63;
        float v = (k < K) ? W[(size_t)k * 128 + ch * 64 + c]
                          : ((k == K) ? b[ch * 64 + c] : 0.f);
        Wt[k * WSTRIDE + c] = wmma::__float_to_tf32(v);
    }
    // A tail cols (ones col at AROW) when bias row beyond AROW
    if (KPAD > AROW) {
        constexpr int TAIL = KPAD - AROW;
        for (int i = threadIdx.x; i < 128 * TAIL; i += 256) {
            int r = i / TAIL, c = AROW + (i - r * TAIL);
            At[r * ASTRIDE + c] = (c == AROW) ? 1.0f : 0.f;
        }
    }
    __syncthreads();

    int warp = threadIdx.x >> 5;
    int wr = warp >> 1;      // 0..3 -> 32 rows each
    int wc = warp & 1;       // 0..1 -> 32 cols each

    wmma::fragment<wmma::accumulator, 16, 16, 8, float> acc[2][2];
#pragma unroll
    for (int i = 0; i < 2; ++i)
#pragma unroll
        for (int j = 0; j < 2; ++j) wmma::fill_fragment(acc[i][j], 0.f);

#pragma unroll
    for (int kk = 0; kk < KPAD / 8; ++kk) {
        wmma::fragment<wmma::matrix_a, 16, 16, 8, wmma::precision::tf32,
                       wmma::row_major> af[2];
#pragma unroll
        for (int i = 0; i < 2; ++i)
            wmma::load_matrix_sync(af[i],
                At + (wr * 32 + i * 16) * ASTRIDE + kk * 8, ASTRIDE);
        wmma::fragment<wmma::matrix_b, 16, 16, 8, wmma::precision::tf32,
                       wmma::row_major> bf[2];
#pragma unroll
        for (int j = 0; j < 2; ++j)
            wmma::load_matrix_sync(bf[j],
                Wt + kk * 8 * WSTRIDE + wc * 32 + j * 16, WSTRIDE);
#pragma unroll
        for (int i = 0; i < 2; ++i)
#pragma unroll
            for (int j = 0; j < 2; ++j)
                wmma::mma_sync(acc[i][j], af[i], bf[j], acc[i][j]);
    }
#pragma unroll
    for (int i = 0; i < 2; ++i)
#pragma unroll
        for (int j = 0; j < 2; ++j)
            wmma::store_matrix_sync(
                out + (size_t)(row0 + wr * 32 + i * 16) * 128 + ch * 64 + wc * 32 + j * 16,
                acc[i][j], 128, wmma::mem_row_major);
}

// ---------------- scan: CSR offsets from degrees ----------------
__global__ void scan1_kernel() {
    __shared__ int s[1024];
    int n = blockIdx.x * 1024 + threadIdx.x;
    int v = (n < NN) ? g_deg[n] : 0;
    s[threadIdx.x] = v;
    __syncthreads();
    for (int off = 1; off < 1024; off <<= 1) {
        int t = (threadIdx.x >= off) ? s[threadIdx.x - off] : 0;
        __syncthreads();
        s[threadIdx.x] += t;
        __syncthreads();
    }
    if (n < NN) g_offs[n] = s[threadIdx.x] - v;
    if (threadIdx.x == 1023) g_bsum[blockIdx.x] = s[1023];
}

__global__ void scan23_kernel(int nb) {
    __shared__ int bsm[128];
    if (threadIdx.x < 128) bsm[threadIdx.x] = (threadIdx.x < nb) ? g_bsum[threadIdx.x] : 0;
    __syncthreads();
    for (int o = 1; o < 128; o <<= 1) {
        int v = 0;
        if (threadIdx.x < 128 && threadIdx.x >= o) v = bsm[threadIdx.x - o];
        __syncthreads();
        if (threadIdx.x < 128) bsm[threadIdx.x] += v;
        __syncthreads();
    }
    int b = blockIdx.x;
    int offset = (b == 0) ? 0 : bsm[b - 1];
    int n = b * 1024 + threadIdx.x;
    if (n < NN) g_offs[n] += offset;
    if (b == 0 && threadIdx.x == 0) g_offs[NN] = NE;
}

// ---------------- scatter (edge id, src) into CSR by dst ----------------
__global__ void scatter_kernel(const int* __restrict__ src,
                               const int* __restrict__ dst) {
    int i = blockIdx.x * blockDim.x + threadIdx.x;
    if (i >= NE) return;
    int node = dst[i];
    int pos = g_offs[node] + atomicAdd(&g_cur[node], 1);
    g_es[pos] = make_int2(i, src[i]);
}

// ---------------- per-edge GATv2 softmax update (one chain) ----------------
__device__ __forceinline__ void edge_update(
    float v, const u64 (&Wp)[13][2], u64 xl01, u64 xl23, u64 xr01, u64 xr23,
    float4 att4, float& m, float& ss, u64& a01, u64& a23)
{
    u64 e01 = 0ull, e23 = 0ull;
#pragma unroll
    for (int j = 0; j < 13; ++j) {
        float f = __shfl_sync(0xffffffffu, v, j);
        u64 ff = pack2(f, f);
        e01 = ffma2(ff, Wp[j][0], e01);
        e23 = ffma2(ff, Wp[j][1], e23);
    }
    u64 z01 = fadd2(fadd2(xl01, xr01), e01);
    u64 z23 = fadd2(fadd2(xl23, xr23), e23);
    float z0, z1, z2, z3;
    unpack2(z01, z0, z1);
    unpack2(z23, z2, z3);
    z0 = fmaxf(z0, 0.2f * z0);
    z1 = fmaxf(z1, 0.2f * z1);
    z2 = fmaxf(z2, 0.2f * z2);
    z3 = fmaxf(z3, 0.2f * z3);
    float p = z0 * att4.x + z1 * att4.y + z2 * att4.z + z3 * att4.w;
    p += __shfl_xor_sync(0xffffffffu, p, 1);
    p += __shfl_xor_sync(0xffffffffu, p, 2);
    p += __shfl_xor_sync(0xffffffffu, p, 4);
    float mn = fmaxf(m, p);
    float so = __expf(m - mn);
    float ex = __expf(p - mn);
    ss = ss * so + ex;
    u64 so2 = pack2(so, so), ex2 = pack2(ex, ex);
    a01 = ffma2(ex2, xl01, fmul2(a01, so2));
    a23 = ffma2(ex2, xl23, fmul2(a23, so2));
    m = mn;
}

// ---------------- fused GATv2 block: 2 interleaved softmax chains per warp ----------------
template <bool BLOCK2>
__global__ void __launch_bounds__(256)
gat_kernel(const float* __restrict__ xl, const float* __restrict__ xr,
           const float* __restrict__ resid, float* __restrict__ hout,
           const float* __restrict__ We, const float* __restrict__ att,
           const float* __restrict__ ab, const float* __restrict__ lng,
           const float* __restrict__ lnb,
           const float* __restrict__ edge_attr, const int* __restrict__ batch) {
    int lane = threadIdx.x & 31;
    int warp = threadIdx.x >> 5;
    int wid = blockIdx.x * 8 + warp;
    int nwarps = gridDim.x * 8;

    u64 Wp[13][2];
#pragma unroll
    for (int j = 0; j < 13; ++j) {
        float4 w = *(const float4*)&We[j * 128 + lane * 4];
        Wp[j][0] = pack2(w.x, w.y);
        Wp[j][1] = pack2(w.z, w.w);
    }

    float4 att4 = ((const float4*)att)[lane];
    float4 ab4  = ((const float4*)ab)[lane];
    float4 lg4  = ((const float4*)lng)[lane];
    float4 lb4  = ((const float4*)lnb)[lane];

    const float4* xl4 = (const float4*)xl;

    for (int n = wid; n < NN; n += nwarps) {
        int off0 = g_offs[n], off1 = g_offs[n + 1];
        float4 xr4 = ((const float4*)xr)[(size_t)n * 32 + lane];
        u64 xr01 = pack2(xr4.x, xr4.y), xr23 = pack2(xr4.z, xr4.w);
        float invdeg = 1.f / fmaxf((float)(off1 - off0), 1.f);

        // two independent online-softmax chains
        float mA = -INFINITY, ssA = 0.f, mB = -INFINITY, ssB = 0.f;
        u64 aA01 = 0ull, aA23 = 0ull, aB01 = 0ull, aB23 = 0ull;
        float vsum = 0.f;

        int idx = off0;
        bool h0 = idx < off1, h1 = idx + 1 < off1;
        int2 e0, e1; float4 x0, x1; float v0 = 0.f, v1 = 0.f;
        if (h0) {
            e0 = g_es[idx];
            x0 = xl4[(size_t)e0.y * 32 + lane];
            v0 = (lane < 13) ? edge_attr[(size_t)e0.x * 13 + lane] : 0.f;
        }
        if (h1) {
            e1 = g_es[idx + 1];
            x1 = xl4[(size_t)e1.y * 32 + lane];
            v1 = (lane < 13) ? edge_attr[(size_t)e1.x * 13 + lane] : 0.f;
        }

        while (h0) {
            // prefetch next pair
            bool nh0 = idx + 2 < off1, nh1 = idx + 3 < off1;
            int2 ne0, ne1; float4 nx0, nx1; float nv0 = 0.f, nv1 = 0.f;
            if (nh0) {
                ne0 = g_es[idx + 2];
                nx0 = xl4[(size_t)ne0.y * 32 + lane];
                nv0 = (lane < 13) ? edge_attr[(size_t)ne0.x * 13 + lane] : 0.f;
            }
            if (nh1) {
                ne1 = g_es[idx + 3];
                nx1 = xl4[(size_t)ne1.y * 32 + lane];
                nv1 = (lane < 13) ? edge_attr[(size_t)ne1.x * 13 + lane] : 0.f;
            }

            vsum += v0;
            u64 x001 = pack2(x0.x, x0.y), x023 = pack2(x0.z, x0.w);
            edge_update(v0, Wp, x001, x023, xr01, xr23, att4, mA, ssA, aA01, aA23);
            if (h1) {
                vsum += v1;
                u64 x101 = pack2(x1.x, x1.y), x123 = pack2(x1.z, x1.w);
                edge_update(v1, Wp, x101, x123, xr01, xr23, att4, mB, ssB, aB01, aB23);
            }

            h0 = nh0; h1 = nh1;
            e0 = ne0; x0 = nx0; v0 = nv0;
            e1 = ne1; x1 = nx1; v1 = nv1;
            idx += 2;
        }

        // merge chains
        float m = fmaxf(mA, mB);
        float fA = (ssA > 0.f) ? __expf(mA - m) : 0.f;
        float fB = (ssB > 0.f) ? __expf(mB - m) : 0.f;
        float ss = ssA * fA + ssB * fB;
        u64 fA2 = pack2(fA, fA), fB2 = pack2(fB, fB);
        u64 a01 = fadd2(fmul2(aA01, fA2), fmul2(aB01, fB2));
        u64 a23 = fadd2(fmul2(aA23, fA2), fmul2(aB23, fB2));
        if (ss == 0.f) m = -INFINITY;   // no edges at all

        // ---- self loop: attr = mean of in-edge attrs, src = n ----
        {
            float vL = vsum * invdeg;
            float4 xls = ((const float4*)xl)[(size_t)n * 32 + lane];
            u64 xl01 = pack2(xls.x, xls.y), xl23 = pack2(xls.z, xls.w);
            edge_update(vL, Wp, xl01, xl23, xr01, xr23, att4, m, ss, a01, a23);
        }

        float a0, a1, a2, a3;
        unpack2(a01, a0, a1);
        unpack2(a23, a2, a3);
        float inv = 1.f / ss;
        float t0 = a0 * inv + ab4.x;
        float t1 = a1 * inv + ab4.y;
        float t2 = a2 * inv + ab4.z;
        float t3 = a3 * inv + ab4.w;
        t0 = t0 > 0.f ? t0 : expm1f(t0);
        t1 = t1 > 0.f ? t1 : expm1f(t1);
        t2 = t2 > 0.f ? t2 : expm1f(t2);
        t3 = t3 > 0.f ? t3 : expm1f(t3);
        float4 r4 = ((const float4*)resid)[(size_t)n * 32 + lane];
        t0 += r4.x; t1 += r4.y; t2 += r4.z; t3 += r4.w;
        float s1 = t0 + t1 + t2 + t3;
#pragma unroll
        for (int o = 1; o < 32; o <<= 1) s1 += __shfl_xor_sync(0xffffffffu, s1, o);
        float mu = s1 * (1.f / 128.f);
        float d0 = t0 - mu, d1 = t1 - mu, d2 = t2 - mu, d3 = t3 - mu;
        float s2 = d0 * d0 + d1 * d1 + d2 * d2 + d3 * d3;
#pragma unroll
        for (int o = 1; o < 32; o <<= 1) s2 += __shfl_xor_sync(0xffffffffu, s2, o);
        float rstd = rsqrtf(s2 * (1.f / 128.f) + 1e-5f);
        float o0 = d0 * rstd * lg4.x + lb4.x;
        float o1 = d1 * rstd * lg4.y + lb4.y;
        float o2 = d2 * rstd * lg4.z + lb4.z;
        float o3 = d3 * rstd * lg4.w + lb4.w;

        if (!BLOCK2) {
            ((float4*)hout)[(size_t)n * 32 + lane] = make_float4(o0, o1, o2, o3);
        } else {
            int g = batch[n];
            float* gs = g_gsum + (size_t)g * 128 + lane * 4;
            atomicAdd(gs + 0, o0);
            atomicAdd(gs + 1, o1);
            atomicAdd(gs + 2, o2);
            atomicAdd(gs + 3, o3);
            if (lane == 0) atomicAdd(&g_gcnt[g], 1);
        }
    }
}

// ---------------- readout: warp per graph ----------------
__global__ void __launch_bounds__(256)
readout_kernel(const float* __restrict__ Wd1, const float* __restrict__ bd1,
               const float* __restrict__ Wd2, const float* __restrict__ bd2,
               float* __restrict__ out) {
    __shared__ float sm[8][128];
    int lane = threadIdx.x & 31;
    int warp = threadIdx.x >> 5;
    int g = blockIdx.x * 8 + warp;
    if (g >= NG) return;

    int cnt = g_gcnt[g];
    float inv = 1.f / fmaxf((float)cnt, 1.f);
    float4 m4 = ((const float4*)g_gsum)[(size_t)g * 32 + lane];
    sm[warp][lane * 4 + 0] = m4.x * inv;
    sm[warp][lane * 4 + 1] = m4.y * inv;
    sm[warp][lane * 4 + 2] = m4.z * inv;
    sm[warp][lane * 4 + 3] = m4.w * inv;
    __syncwarp();

    float h0 = bd1[lane], h1 = bd1[lane + 32];
#pragma unroll 4
    for (int d = 0; d < 128; ++d) {
        float md = sm[warp][d];
        h0 += md * Wd1[d * 64 + lane];
        h1 += md * Wd1[d * 64 + lane + 32];
    }
    h0 = fmaxf(h0, 0.f);
    h1 = fmaxf(h1, 0.f);
    float p = h0 * Wd2[lane] + h1 * Wd2[lane + 32];
#pragma unroll
    for (int o = 1; o < 32; o <<= 1) p += __shfl_xor_sync(0xffffffffu, p, o);
    if (lane == 0) out[g] = p + bd2[0];
}

// ---------------- launch ----------------
extern "C" void kernel_launch(void* const* d_in, const int* in_sizes, int n_in,
                              void* d_out, int out_size) {
    const float* x         = (const float*)d_in[0];
    const int*   edge_idx  = (const int*)d_in[1];
    const float* edge_attr = (const float*)d_in[2];
    const int*   batch     = (const int*)d_in[3];
    const float* Wl1 = (const float*)d_in[4];
    const float* bl1 = (const float*)d_in[5];
    const float* Wr1 = (const float*)d_in[6];
    const float* br1 = (const float*)d_in[7];
    const float* We1 = (const float*)d_in[8];
    const float* att1 = (const float*)d_in[9];
    const float* ab1 = (const float*)d_in[10];
    const float* lng1 = (const float*)d_in[11];
    const float* lnb1 = (const float*)d_in[12];
    const float* Wres = (const float*)d_in[13];
    const float* bres = (const float*)d_in[14];
    const float* Wl2 = (const float*)d_in[15];
    const float* bl2 = (const float*)d_in[16];
    const float* Wr2 = (const float*)d_in[17];
    const float* br2 = (const float*)d_in[18];
    const float* We2 = (const float*)d_in[19];
    const float* att2 = (const float*)d_in[20];
    const float* ab2 = (const float*)d_in[21];
    const float* lng2 = (const float*)d_in[22];
    const float* lnb2 = (const float*)d_in[23];
    const float* Wd1 = (const float*)d_in[24];
    const float* bd1 = (const float*)d_in[25];
    const float* Wd2 = (const float*)d_in[26];
    const float* bd2 = (const float*)d_in[27];
    float* out = (float*)d_out;

    const int* src = edge_idx;
    const int* dst = edge_idx + NE;

    float *p_xpad, *p_xl, *p_xr, *p_xres, *p_h;
    cudaGetSymbolAddress((void**)&p_xpad, g_xpad);
    cudaGetSymbolAddress((void**)&p_xl, g_xl);
    cudaGetSymbolAddress((void**)&p_xr, g_xr);
    cudaGetSymbolAddress((void**)&p_xres, g_xres);
    cudaGetSymbolAddress((void**)&p_h, g_h);

    int smem1 = (40 * 68 + 128 * 48) * 4;     // 35456 B
    int smem2 = (136 * 68 + 128 * 144) * 4;   // 110720 B
    cudaFuncSetAttribute((const void*)mm_tc<38, 40, 40, 48>,
                         cudaFuncAttributeMaxDynamicSharedMemorySize, smem1);
    cudaFuncSetAttribute((const void*)mm_tc<128, 136, 128, 144>,
                         cudaFuncAttributeMaxDynamicSharedMemorySize, smem2);

    int nb = (NN + 1023) / 1024;
    // launch order: slot 4 (ncu-sampled) = block-1 GEMM
    setup_kernel<<<(NN_PAD * 40 + 255) / 256, 256>>>(x);
    deg_kernel<<<(NE + 255) / 256, 256>>>(dst);
    scan1_kernel<<<nb, 1024>>>();
    mm_tc<38, 40, 40, 48><<<dim3(RT128, 6), 256, smem1>>>(
        p_xpad, Wl1, bl1, p_xl, Wr1, br1, p_xr, Wres, bres, p_xres);
    scan23_kernel<<<nb, 1024>>>(nb);
    scatter_kernel<<<(NE + 255) / 256, 256>>>(src, dst);
    gat_kernel<false><<<2048, 256>>>(p_xl, p_xr, p_xres, p_h,
                                     We1, att1, ab1, lng1, lnb1,
                                     edge_attr, nullptr);
    mm_tc<128, 136, 128, 144><<<dim3(RT128, 4), 256, smem2>>>(
        p_h, Wl2, bl2, p_xl, Wr2, br2, p_xr, Wr2, br2, p_xr);
    gat_kernel<true><<<2048, 256>>>(p_xl, p_xr, p_h, nullptr,
                                    We2, att2, ab2, lng2, lnb2,
                                    edge_attr, batch);
    readout_kernel<<<(NG + 7) / 8, 256>>>(Wd1, bd1, Wd2, bd2, out);
}

// round 8
// speedup vs baseline: 1.1124x; 1.0115x over previous
#include <cuda_runtime.h>
#include <mma.h>
#include <math.h>
#include <cstdint>

using namespace nvcuda;

#define NN 100000
#define NN_PAD 100096
#define NE 400000
#define NG 4096
#define RT128 782           // ceil(NN/128); 782*128 == 100096

typedef unsigned long long u64;

__device__ __forceinline__ u64 pack2(float x, float y) {
    u64 r; asm("mov.b64 %0,{%1,%2};" : "=l"(r) : "f"(x), "f"(y)); return r;
}
__device__ __forceinline__ void unpack2(u64 v, float& x, float& y) {
    asm("mov.b64 {%0,%1},%2;" : "=f"(x), "=f"(y) : "l"(v));
}
__device__ __forceinline__ u64 ffma2(u64 a, u64 b, u64 c) {
    u64 d; asm("fma.rn.f32x2 %0,%1,%2,%3;" : "=l"(d) : "l"(a), "l"(b), "l"(c)); return d;
}
__device__ __forceinline__ u64 fadd2(u64 a, u64 b) {
    u64 d; asm("add.rn.f32x2 %0,%1,%2;" : "=l"(d) : "l"(a), "l"(b)); return d;
}
__device__ __forceinline__ u64 fmul2(u64 a, u64 b) {
    u64 d; asm("mul.rn.f32x2 %0,%1,%2;" : "=l"(d) : "l"(a), "l"(b)); return d;
}

// ---------------- scratch (static __device__ — no allocations) ----------------
__device__ float g_xpad[(size_t)NN_PAD * 40];   // tf32-rounded x, ones col at 38
__device__ float g_xl[(size_t)NN_PAD * 128];
__device__ float g_xr[(size_t)NN_PAD * 128];
__device__ float g_xres[(size_t)NN_PAD * 128];
__device__ float g_h[(size_t)NN_PAD * 128];     // exact h (residual path)
__device__ float g_htf[(size_t)NN_PAD * 128];   // tf32-rounded h (GEMM2 A operand)
__device__ int   g_deg[NN];
__device__ int   g_cur[NN];
__device__ int   g_offs[NN + 1];
__device__ int2  g_es[NE];       // (edge id, src node)
__device__ int   g_bsum[128];
__device__ float g_gsum[(size_t)NG * 128];
__device__ int   g_gcnt[NG];

// ---------------- setup: pad x (tf32-rounded, stride 40, ones col 38) + zero ----------------
__global__ void setup_kernel(const float* __restrict__ x) {
    int i = blockIdx.x * blockDim.x + threadIdx.x;
    if (i < NN_PAD * 40) {
        int r = i / 40, c = i - r * 40;
        float v;
        if (r < NN && c < 38)      v = wmma::__float_to_tf32(x[(size_t)r * 38 + c]);
        else if (c == 38)          v = 1.0f;
        else                       v = 0.0f;
        g_xpad[i] = v;
    }
    if (i < NN) { g_deg[i] = 0; g_cur[i] = 0; }
    if (i < NG * 128) g_gsum[i] = 0.f;
    if (i < NG) g_gcnt[i] = 0;
}

// ---------------- degree ----------------
__global__ void deg_kernel(const int* __restrict__ dst) {
    int e = blockIdx.x * blockDim.x + threadIdx.x;
    if (e < NE) atomicAdd(&g_deg[dst[e]], 1);
}

// ---------------- tensor-core tf32 GEMM, 128x64 block tile, 32x32 warp tile ----------------
// A already tf32-rounded in gmem. No conversions in the kernel hot path.
// ASTRIDE ≡ 12 (mod 32) to break 8-way bank conflicts on A-fragment loads.
template <int K, int KPAD, int AROW, int ASTRIDE>
__global__ void __launch_bounds__(256)
mm_tc(const float* __restrict__ A,
      const float* __restrict__ Wa, const float* __restrict__ ba, float* __restrict__ oa,
      const float* __restrict__ Wb, const float* __restrict__ bb, float* __restrict__ ob,
      const float* __restrict__ Wc, const float* __restrict__ bc, float* __restrict__ oc) {
    constexpr int WSTRIDE = 68;
    extern __shared__ float sm[];
    float* Wt = sm;                       // KPAD x 68
    float* At = sm + KPAD * WSTRIDE;      // 128 x ASTRIDE

    int set = blockIdx.y >> 1;
    int ch  = blockIdx.y & 1;
    const float* W = (set == 0) ? Wa : (set == 1) ? Wb : Wc;
    const float* b = (set == 0) ? ba : (set == 1) ? bb : bc;
    float* out     = (set == 0) ? oa : (set == 1) ? ob : oc;

    int row0 = blockIdx.x * 128;

    // A tile via cp.async (raw copy — values pre-rounded to tf32)
    {
        constexpr int SEGS = AROW / 4;
        for (int i = threadIdx.x; i < 128 * SEGS; i += 256) {
            int r = i / SEGS, seg = i - r * SEGS;
            unsigned d = (unsigned)__cvta_generic_to_shared(At + r * ASTRIDE + seg * 4);
            const float* s = A + (size_t)(row0 + r) * AROW + seg * 4;
            asm volatile("cp.async.cg.shared.global [%0], [%1], 16;" :: "r"(d), "l"(s));
        }
        asm volatile("cp.async.commit_group;");
    }
    // W slice (64 cols), bias row at K, zeros above (converted once here)
    for (int i = threadIdx.x; i < KPAD * 64; i += 256) {
        int k = i >> 6, c = i & 63;
        float v = (k < K) ? W[(size_t)k * 128 + ch * 64 + c]
                          : ((k == K) ? b[ch * 64 + c] : 0.f);
        Wt[k * WSTRIDE + c] = wmma::__float_to_tf32(v);
    }
    // A tail cols (ones col at AROW) when bias row beyond AROW
    if (KPAD > AROW) {
        constexpr int TAIL = KPAD - AROW;
        for (int i = threadIdx.x; i < 128 * TAIL; i += 256) {
            int r = i / TAIL, c = AROW + (i - r * TAIL);
            At[r * ASTRIDE + c] = (c == AROW) ? 1.0f : 0.f;
        }
    }
    asm volatile("cp.async.wait_group 0;");
    __syncthreads();

    int warp = threadIdx.x >> 5;
    int wr = warp >> 1;      // 0..3 -> 32 rows each
    int wc = warp & 1;       // 0..1 -> 32 cols each

    wmma::fragment<wmma::accumulator, 16, 16, 8, float> acc[2][2];
#pragma unroll
    for (int i = 0; i < 2; ++i)
#pragma unroll
        for (int j = 0; j < 2; ++j) wmma::fill_fragment(acc[i][j], 0.f);

#pragma unroll
    for (int kk = 0; kk < KPAD / 8; ++kk) {
        wmma::fragment<wmma::matrix_a, 16, 16, 8, wmma::precision::tf32,
                       wmma::row_major> af[2];
#pragma unroll
        for (int i = 0; i < 2; ++i)
            wmma::load_matrix_sync(af[i],
                At + (wr * 32 + i * 16) * ASTRIDE + kk * 8, ASTRIDE);
        wmma::fragment<wmma::matrix_b, 16, 16, 8, wmma::precision::tf32,
                       wmma::row_major> bf[2];
#pragma unroll
        for (int j = 0; j < 2; ++j)
            wmma::load_matrix_sync(bf[j],
                Wt + kk * 8 * WSTRIDE + wc * 32 + j * 16, WSTRIDE);
#pragma unroll
        for (int i = 0; i < 2; ++i)
#pragma unroll
            for (int j = 0; j < 2; ++j)
                wmma::mma_sync(acc[i][j], af[i], bf[j], acc[i][j]);
    }
#pragma unroll
    for (int i = 0; i < 2; ++i)
#pragma unroll
        for (int j = 0; j < 2; ++j)
            wmma::store_matrix_sync(
                out + (size_t)(row0 + wr * 32 + i * 16) * 128 + ch * 64 + wc * 32 + j * 16,
                acc[i][j], 128, wmma::mem_row_major);
}

// ---------------- scan: CSR offsets from degrees ----------------
__global__ void scan1_kernel() {
    __shared__ int s[1024];
    int n = blockIdx.x * 1024 + threadIdx.x;
    int v = (n < NN) ? g_deg[n] : 0;
    s[threadIdx.x] = v;
    __syncthreads();
    for (int off = 1; off < 1024; off <<= 1) {
        int t = (threadIdx.x >= off) ? s[threadIdx.x - off] : 0;
        __syncthreads();
        s[threadIdx.x] += t;
        __syncthreads();
    }
    if (n < NN) g_offs[n] = s[threadIdx.x] - v;
    if (threadIdx.x == 1023) g_bsum[blockIdx.x] = s[1023];
}

__global__ void scan23_kernel(int nb) {
    __shared__ int bsm[128];
    if (threadIdx.x < 128) bsm[threadIdx.x] = (threadIdx.x < nb) ? g_bsum[threadIdx.x] : 0;
    __syncthreads();
    for (int o = 1; o < 128; o <<= 1) {
        int v = 0;
        if (threadIdx.x < 128 && threadIdx.x >= o) v = bsm[threadIdx.x - o];
        __syncthreads();
        if (threadIdx.x < 128) bsm[threadIdx.x] += v;
        __syncthreads();
    }
    int b = blockIdx.x;
    int offset = (b == 0) ? 0 : bsm[b - 1];
    int n = b * 1024 + threadIdx.x;
    if (n < NN) g_offs[n] += offset;
    if (b == 0 && threadIdx.x == 0) g_offs[NN] = NE;
}

// ---------------- scatter (edge id, src) into CSR by dst ----------------
__global__ void scatter_kernel(const int* __restrict__ src,
                               const int* __restrict__ dst) {
    int i = blockIdx.x * blockDim.x + threadIdx.x;
    if (i >= NE) return;
    int node = dst[i];
    int pos = g_offs[node] + atomicAdd(&g_cur[node], 1);
    g_es[pos] = make_int2(i, src[i]);
}

// ---------------- per-edge GATv2 softmax update (one chain) ----------------
__device__ __forceinline__ void edge_update(
    float v, const u64 (&Wp)[13][2], u64 xl01, u64 xl23, u64 xr01, u64 xr23,
    float4 att4, float& m, float& ss, u64& a01, u64& a23)
{
    u64 e01 = 0ull, e23 = 0ull;
#pragma unroll
    for (int j = 0; j < 13; ++j) {
        float f = __shfl_sync(0xffffffffu, v, j);
        u64 ff = pack2(f, f);
        e01 = ffma2(ff, Wp[j][0], e01);
        e23 = ffma2(ff, Wp[j][1], e23);
    }
    u64 z01 = fadd2(fadd2(xl01, xr01), e01);
    u64 z23 = fadd2(fadd2(xl23, xr23), e23);
    float z0, z1, z2, z3;
    unpack2(z01, z0, z1);
    unpack2(z23, z2, z3);
    z0 = fmaxf(z0, 0.2f * z0);
    z1 = fmaxf(z1, 0.2f * z1);
    z2 = fmaxf(z2, 0.2f * z2);
    z3 = fmaxf(z3, 0.2f * z3);
    float p = z0 * att4.x + z1 * att4.y + z2 * att4.z + z3 * att4.w;
    p += __shfl_xor_sync(0xffffffffu, p, 1);
    p += __shfl_xor_sync(0xffffffffu, p, 2);
    p += __shfl_xor_sync(0xffffffffu, p, 4);
    float mn = fmaxf(m, p);
    float so = __expf(m - mn);
    float ex = __expf(p - mn);
    ss = ss * so + ex;
    u64 so2 = pack2(so, so), ex2 = pack2(ex, ex);
    a01 = ffma2(ex2, xl01, fmul2(a01, so2));
    a23 = ffma2(ex2, xl23, fmul2(a23, so2));
    m = mn;
}

// ---------------- fused GATv2 block: 2 interleaved softmax chains per warp ----------------
// BLOCK2=false: also writes a tf32-rounded copy of h for the next GEMM.
template <bool BLOCK2>
__global__ void __launch_bounds__(256)
gat_kernel(const float* __restrict__ xl, const float* __restrict__ xr,
           const float* __restrict__ resid, float* __restrict__ hout,
           float* __restrict__ houttf,
           const float* __restrict__ We, const float* __restrict__ att,
           const float* __restrict__ ab, const float* __restrict__ lng,
           const float* __restrict__ lnb,
           const float* __restrict__ edge_attr, const int* __restrict__ batch) {
    int lane = threadIdx.x & 31;
    int warp = threadIdx.x >> 5;
    int wid = blockIdx.x * 8 + warp;
    int nwarps = gridDim.x * 8;

    u64 Wp[13][2];
#pragma unroll
    for (int j = 0; j < 13; ++j) {
        float4 w = *(const float4*)&We[j * 128 + lane * 4];
        Wp[j][0] = pack2(w.x, w.y);
        Wp[j][1] = pack2(w.z, w.w);
    }

    float4 att4 = ((const float4*)att)[lane];
    float4 ab4  = ((const float4*)ab)[lane];
    float4 lg4  = ((const float4*)lng)[lane];
    float4 lb4  = ((const float4*)lnb)[lane];

    const float4* xl4 = (const float4*)xl;

    for (int n = wid; n < NN; n += nwarps) {
        int off0 = g_offs[n], off1 = g_offs[n + 1];
        float4 xr4 = ((const float4*)xr)[(size_t)n * 32 + lane];
        u64 xr01 = pack2(xr4.x, xr4.y), xr23 = pack2(xr4.z, xr4.w);
        float invdeg = 1.f / fmaxf((float)(off1 - off0), 1.f);

        float mA = -INFINITY, ssA = 0.f, mB = -INFINITY, ssB = 0.f;
        u64 aA01 = 0ull, aA23 = 0ull, aB01 = 0ull, aB23 = 0ull;
        float vsum = 0.f;

        int idx = off0;
        bool h0 = idx < off1, h1 = idx + 1 < off1;
        int2 e0, e1; float4 x0, x1; float v0 = 0.f, v1 = 0.f;
        if (h0) {
            e0 = g_es[idx];
            x0 = xl4[(size_t)e0.y * 32 + lane];
            v0 = (lane < 13) ? edge_attr[(size_t)e0.x * 13 + lane] : 0.f;
        }
        if (h1) {
            e1 = g_es[idx + 1];
            x1 = xl4[(size_t)e1.y * 32 + lane];
            v1 = (lane < 13) ? edge_attr[(size_t)e1.x * 13 + lane] : 0.f;
        }

        while (h0) {
            bool nh0 = idx + 2 < off1, nh1 = idx + 3 < off1;
            int2 ne0, ne1; float4 nx0, nx1; float nv0 = 0.f, nv1 = 0.f;
            if (nh0) {
                ne0 = g_es[idx + 2];
                nx0 = xl4[(size_t)ne0.y * 32 + lane];
                nv0 = (lane < 13) ? edge_attr[(size_t)ne0.x * 13 + lane] : 0.f;
            }
            if (nh1) {
                ne1 = g_es[idx + 3];
                nx1 = xl4[(size_t)ne1.y * 32 + lane];
                nv1 = (lane < 13) ? edge_attr[(size_t)ne1.x * 13 + lane] : 0.f;
            }

            vsum += v0;
            u64 x001 = pack2(x0.x, x0.y), x023 = pack2(x0.z, x0.w);
            edge_update(v0, Wp, x001, x023, xr01, xr23, att4, mA, ssA, aA01, aA23);
            if (h1) {
                vsum += v1;
                u64 x101 = pack2(x1.x, x1.y), x123 = pack2(x1.z, x1.w);
                edge_update(v1, Wp, x101, x123, xr01, xr23, att4, mB, ssB, aB01, aB23);
            }

            h0 = nh0; h1 = nh1;
            e0 = ne0; x0 = nx0; v0 = nv0;
            e1 = ne1; x1 = nx1; v1 = nv1;
            idx += 2;
        }

        // merge chains
        float m = fmaxf(mA, mB);
        float fA = (ssA > 0.f) ? __expf(mA - m) : 0.f;
        float fB = (ssB > 0.f) ? __expf(mB - m) : 0.f;
        float ss = ssA * fA + ssB * fB;
        u64 fA2 = pack2(fA, fA), fB2 = pack2(fB, fB);
        u64 a01 = fadd2(fmul2(aA01, fA2), fmul2(aB01, fB2));
        u64 a23 = fadd2(fmul2(aA23, fA2), fmul2(aB23, fB2));
        if (ss == 0.f) m = -INFINITY;

        // ---- self loop: attr = mean of in-edge attrs, src = n ----
        {
            float vL = vsum * invdeg;
            float4 xls = ((const float4*)xl)[(size_t)n * 32 + lane];
            u64 xl01 = pack2(xls.x, xls.y), xl23 = pack2(xls.z, xls.w);
            edge_update(vL, Wp, xl01, xl23, xr01, xr23, att4, m, ss, a01, a23);
        }

        float a0, a1, a2, a3;
        unpack2(a01, a0, a1);
        unpack2(a23, a2, a3);
        float inv = 1.f / ss;
        float t0 = a0 * inv + ab4.x;
        float t1 = a1 * inv + ab4.y;
        float t2 = a2 * inv + ab4.z;
        float t3 = a3 * inv + ab4.w;
        t0 = t0 > 0.f ? t0 : expm1f(t0);
        t1 = t1 > 0.f ? t1 : expm1f(t1);
        t2 = t2 > 0.f ? t2 : expm1f(t2);
        t3 = t3 > 0.f ? t3 : expm1f(t3);
        float4 r4 = ((const float4*)resid)[(size_t)n * 32 + lane];
        t0 += r4.x; t1 += r4.y; t2 += r4.z; t3 += r4.w;
        float s1 = t0 + t1 + t2 + t3;
#pragma unroll
        for (int o = 1; o < 32; o <<= 1) s1 += __shfl_xor_sync(0xffffffffu, s1, o);
        float mu = s1 * (1.f / 128.f);
        float d0 = t0 - mu, d1 = t1 - mu, d2 = t2 - mu, d3 = t3 - mu;
        float s2 = d0 * d0 + d1 * d1 + d2 * d2 + d3 * d3;
#pragma unroll
        for (int o = 1; o < 32; o <<= 1) s2 += __shfl_xor_sync(0xffffffffu, s2, o);
        float rstd = rsqrtf(s2 * (1.f / 128.f) + 1e-5f);
        float o0 = d0 * rstd * lg4.x + lb4.x;
        float o1 = d1 * rstd * lg4.y + lb4.y;
        float o2 = d2 * rstd * lg4.z + lb4.z;
        float o3 = d3 * rstd * lg4.w + lb4.w;

        if (!BLOCK2) {
            ((float4*)hout)[(size_t)n * 32 + lane] = make_float4(o0, o1, o2, o3);
            ((float4*)houttf)[(size_t)n * 32 + lane] = make_float4(
                wmma::__float_to_tf32(o0), wmma::__float_to_tf32(o1),
                wmma::__float_to_tf32(o2), wmma::__float_to_tf32(o3));
        } else {
            int g = batch[n];
            float* gs = g_gsum + (size_t)g * 128 + lane * 4;
            atomicAdd(gs + 0, o0);
            atomicAdd(gs + 1, o1);
            atomicAdd(gs + 2, o2);
            atomicAdd(gs + 3, o3);
            if (lane == 0) atomicAdd(&g_gcnt[g], 1);
        }
    }
}

// ---------------- readout: warp per graph ----------------
__global__ void __launch_bounds__(256)
readout_kernel(const float* __restrict__ Wd1, const float* __restrict__ bd1,
               const float* __restrict__ Wd2, const float* __restrict__ bd2,
               float* __restrict__ out) {
    __shared__ float sm[8][128];
    int lane = threadIdx.x & 31;
    int warp = threadIdx.x >> 5;
    int g = blockIdx.x * 8 + warp;
    if (g >= NG) return;

    int cnt = g_gcnt[g];
    float inv = 1.f / fmaxf((float)cnt, 1.f);
    float4 m4 = ((const float4*)g_gsum)[(size_t)g * 32 + lane];
    sm[warp][lane * 4 + 0] = m4.x * inv;
    sm[warp][lane * 4 + 1] = m4.y * inv;
    sm[warp][lane * 4 + 2] = m4.z * inv;
    sm[warp][lane * 4 + 3] = m4.w * inv;
    __syncwarp();

    float h0 = bd1[lane], h1 = bd1[lane + 32];
#pragma unroll 4
    for (int d = 0; d < 128; ++d) {
        float md = sm[warp][d];
        h0 += md * Wd1[d * 64 + lane];
        h1 += md * Wd1[d * 64 + lane + 32];
    }
    h0 = fmaxf(h0, 0.f);
    h1 = fmaxf(h1, 0.f);
    float p = h0 * Wd2[lane] + h1 * Wd2[lane + 32];
#pragma unroll
    for (int o = 1; o < 32; o <<= 1) p += __shfl_xor_sync(0xffffffffu, p, o);
    if (lane == 0) out[g] = p + bd2[0];
}

// ---------------- launch ----------------
extern "C" void kernel_launch(void* const* d_in, const int* in_sizes, int n_in,
                              void* d_out, int out_size) {
    const float* x         = (const float*)d_in[0];
    const int*   edge_idx  = (const int*)d_in[1];
    const float* edge_attr = (const float*)d_in[2];
    const int*   batch     = (const int*)d_in[3];
    const float* Wl1 = (const float*)d_in[4];
    const float* bl1 = (const float*)d_in[5];
    const float* Wr1 = (const float*)d_in[6];
    const float* br1 = (const float*)d_in[7];
    const float* We1 = (const float*)d_in[8];
    const float* att1 = (const float*)d_in[9];
    const float* ab1 = (const float*)d_in[10];
    const float* lng1 = (const float*)d_in[11];
    const float* lnb1 = (const float*)d_in[12];
    const float* Wres = (const float*)d_in[13];
    const float* bres = (const float*)d_in[14];
    const float* Wl2 = (const float*)d_in[15];
    const float* bl2 = (const float*)d_in[16];
    const float* Wr2 = (const float*)d_in[17];
    const float* br2 = (const float*)d_in[18];
    const float* We2 = (const float*)d_in[19];
    const float* att2 = (const float*)d_in[20];
    const float* ab2 = (const float*)d_in[21];
    const float* lng2 = (const float*)d_in[22];
    const float* lnb2 = (const float*)d_in[23];
    const float* Wd1 = (const float*)d_in[24];
    const float* bd1 = (const float*)d_in[25];
    const float* Wd2 = (const float*)d_in[26];
    const float* bd2 = (const float*)d_in[27];
    float* out = (float*)d_out;

    const int* src = edge_idx;
    const int* dst = edge_idx + NE;

    float *p_xpad, *p_xl, *p_xr, *p_xres, *p_h, *p_htf;
    cudaGetSymbolAddress((void**)&p_xpad, g_xpad);
    cudaGetSymbolAddress((void**)&p_xl, g_xl);
    cudaGetSymbolAddress((void**)&p_xr, g_xr);
    cudaGetSymbolAddress((void**)&p_xres, g_xres);
    cudaGetSymbolAddress((void**)&p_h, g_h);
    cudaGetSymbolAddress((void**)&p_htf, g_htf);

    int smem1 = (40 * 68 + 128 * 44) * 4;     // 33408 B
    int smem2 = (136 * 68 + 128 * 140) * 4;   // 108672 B
    cudaFuncSetAttribute((const void*)mm_tc<38, 40, 40, 44>,
                         cudaFuncAttributeMaxDynamicSharedMemorySize, smem1);
    cudaFuncSetAttribute((const void*)mm_tc<128, 136, 128, 140>,
                         cudaFuncAttributeMaxDynamicSharedMemorySize, smem2);

    int nb = (NN + 1023) / 1024;
    // launch order: slot 3 (ncu-sampled) = block-1 GEMM
    setup_kernel<<<(NN_PAD * 40 + 255) / 256, 256>>>(x);
    deg_kernel<<<(NE + 255) / 256, 256>>>(dst);
    scan1_kernel<<<nb, 1024>>>();
    mm_tc<38, 40, 40, 44><<<dim3(RT128, 6), 256, smem1>>>(
        p_xpad, Wl1, bl1, p_xl, Wr1, br1, p_xr, Wres, bres, p_xres);
    scan23_kernel<<<nb, 1024>>>(nb);
    scatter_kernel<<<(NE + 255) / 256, 256>>>(src, dst);
    gat_kernel<false><<<2048, 256>>>(p_xl, p_xr, p_xres, p_h, p_htf,
                                     We1, att1, ab1, lng1, lnb1,
                                     edge_attr, nullptr);
    mm_tc<128, 136, 128, 140><<<dim3(RT128, 4), 256, smem2>>>(
        p_htf, Wl2, bl2, p_xl, Wr2, br2, p_xr, Wr2, br2, p_xr);
    gat_kernel<true><<<2048, 256>>>(p_xl, p_xr, p_h, nullptr, nullptr,
                                    We2, att2, ab2, lng2, lnb2,
                                    edge_attr, batch);
    readout_kernel<<<(NG + 7) / 8, 256>>>(Wd1, bd1, Wd2, bd2, out);
}